// round 16
// baseline (speedup 1.0000x reference)
#include <cuda_runtime.h>
#include <math.h>
#include <stdint.h>

#define B_  4
#define C_  256
#define N_  4096
#define CQ_ 64
#define SQRT_LOG2E 1.2011224087864498f   // sqrt(log2(e))

// ---------------- scratch (static __device__ — no allocations allowed) ---------
__device__ float g_P[B_*CQ_*N_];     // P' = sqrt(log2e) * w_qk @ x  (4 MB)
__device__ float g_V[B_*C_*N_];      // V' = tf32r((w_v@x + b_v)*rinv) (16 MB)
__device__ float g_R[B_*C_*N_];      // x - new_features             (16 MB)
__device__ float g_diag[B_*N_];      // c'_n = ||P'_n||^2
__device__ float g_rinv[B_*N_];      // 1 / rowsum

// ---------------- helpers -------------------------------------------------------
__device__ __forceinline__ uint32_t f2tf(float x) {
    uint32_t r;
    asm("cvt.rna.tf32.f32 %0, %1;" : "=r"(r) : "f"(x));
    return r;
}
__device__ __forceinline__ float tf32r(float x) { return __uint_as_float(f2tf(x)); }
__device__ __forceinline__ float ex2(float x) {
    float y;
    asm("ex2.approx.ftz.f32 %0, %1;" : "=f"(y) : "f"(x));
    return y;
}
__device__ __forceinline__ void mma_tf32(float* d,
    uint32_t a0, uint32_t a1, uint32_t a2, uint32_t a3,
    uint32_t b0, uint32_t b1)
{
    asm("mma.sync.aligned.m16n8k8.row.col.f32.tf32.tf32.f32 "
        "{%0,%1,%2,%3}, {%4,%5,%6,%7}, {%8,%9}, {%0,%1,%2,%3};"
        : "+f"(d[0]), "+f"(d[1]), "+f"(d[2]), "+f"(d[3])
        : "r"(a0), "r"(a1), "r"(a2), "r"(a3), "r"(b0), "r"(b1));
}
__device__ __forceinline__ void ldsm4(uint32_t& r0, uint32_t& r1, uint32_t& r2, uint32_t& r3,
                                      uint32_t addr)
{
    asm volatile("ldmatrix.sync.aligned.m8n8.x4.shared.b16 {%0,%1,%2,%3}, [%4];"
        : "=r"(r0), "=r"(r1), "=r"(r2), "=r"(r3) : "r"(addr));
}
__device__ __forceinline__ uint32_t s2u(const void* p) {
    uint32_t a;
    asm("{ .reg .u64 t; cvta.to.shared.u64 t, %1; cvt.u32.u64 %0, t; }" : "=r"(a) : "l"(p));
    return a;
}

// ---------------- P projection: 4-term split tf32 (fp32-equivalent precision) ---
// A-side fragments via ldmatrix (Wh/Wl stored [m][k], ldsm-compatible).
__global__ __launch_bounds__(256, 2) void pgemm_kernel(
    const float* __restrict__ W, const float* __restrict__ X,
    float* __restrict__ Co)
{
    extern __shared__ float sh[];
    float* Wh = sh;                  // [64][68]
    float* Wl = Wh + 64 * 68;        // [64][68]
    float* Xh = Wl + 64 * 68;        // [64][136]
    float* Xl = Xh + 64 * 136;       // [64][136]

    const int t    = threadIdx.x;
    const int w    = t >> 5;
    const int lane = t & 31;
    const int g    = lane >> 2;
    const int tig  = lane & 3;
    const int mg   = (w & 1) * 32;
    const int ng   = (w >> 1) * 32;
    const int n0   = blockIdx.x * 128;
    const int arow = lane & 15;
    const int ak   = (lane >> 4) << 2;
    const float* Xb = X + (long long)blockIdx.y * C_ * N_;
    float*       Cb = Co + (long long)blockIdx.y * CQ_ * N_;
    const uint32_t wh_u = s2u(Wh), wl_u = s2u(Wl);

    float acc[2][4][4];
#pragma unroll
    for (int i = 0; i < 2; i++)
#pragma unroll
        for (int j = 0; j < 4; j++)
#pragma unroll
            for (int q = 0; q < 4; q++) acc[i][j][q] = 0.f;

    for (int kc0 = 0; kc0 < 256; kc0 += 64) {
        __syncthreads();
#pragma unroll
        for (int i = 0; i < 4; i++) {
            int idx = t + i * 256; int r = idx >> 4, c4 = (idx & 15) << 2;
            float4 v = *(const float4*)(W + r * 256 + kc0 + c4);
            v.x *= SQRT_LOG2E; v.y *= SQRT_LOG2E; v.z *= SQRT_LOG2E; v.w *= SQRT_LOG2E;
            float4 h; h.x = tf32r(v.x); h.y = tf32r(v.y); h.z = tf32r(v.z); h.w = tf32r(v.w);
            float4 l; l.x = v.x - h.x; l.y = v.y - h.y; l.z = v.z - h.z; l.w = v.w - h.w;
            *(float4*)&Wh[r * 68 + c4] = h;
            *(float4*)&Wl[r * 68 + c4] = l;
        }
#pragma unroll
        for (int i = 0; i < 8; i++) {
            int idx = t + i * 256; int r = idx >> 5, c4 = (idx & 31) << 2;
            float4 v = *(const float4*)(Xb + (long long)(kc0 + r) * N_ + n0 + c4);
            float4 h; h.x = tf32r(v.x); h.y = tf32r(v.y); h.z = tf32r(v.z); h.w = tf32r(v.w);
            float4 l; l.x = v.x - h.x; l.y = v.y - h.y; l.z = v.z - h.z; l.w = v.w - h.w;
            *(float4*)&Xh[r * 136 + c4] = h;
            *(float4*)&Xl[r * 136 + c4] = l;
        }
        __syncthreads();

#pragma unroll
        for (int kk = 0; kk < 64; kk += 8) {
            uint32_t bh0[4], bh1[4], bl0[4], bl1[4];
#pragma unroll
            for (int j = 0; j < 4; j++) {
                int col = ng + j * 8 + g;
                bh0[j] = __float_as_uint(Xh[(kk + tig)     * 136 + col]);
                bh1[j] = __float_as_uint(Xh[(kk + tig + 4) * 136 + col]);
                bl0[j] = __float_as_uint(Xl[(kk + tig)     * 136 + col]);
                bl1[j] = __float_as_uint(Xl[(kk + tig + 4) * 136 + col]);
            }
#pragma unroll
            for (int s2 = 0; s2 < 2; s2++) {
                int row = mg + s2 * 16;
                uint32_t off = (uint32_t)((row + arow) * 68 + kk + ak) * 4u;
                uint32_t ah0, ah1, ah2, ah3, al0, al1, al2, al3;
                ldsm4(ah0, ah1, ah2, ah3, wh_u + off);
                ldsm4(al0, al1, al2, al3, wl_u + off);
#pragma unroll
                for (int j = 0; j < 4; j++) {
                    mma_tf32(acc[s2][j], ah0, ah1, ah2, ah3, bh0[j], bh1[j]);
                    mma_tf32(acc[s2][j], ah0, ah1, ah2, ah3, bl0[j], bl1[j]);
                    mma_tf32(acc[s2][j], al0, al1, al2, al3, bh0[j], bh1[j]);
                    mma_tf32(acc[s2][j], al0, al1, al2, al3, bl0[j], bl1[j]);
                }
            }
        }
    }

#pragma unroll
    for (int s2 = 0; s2 < 2; s2++) {
        int m0r = mg + s2 * 16 + g;
#pragma unroll
        for (int j = 0; j < 4; j++) {
            long long m = n0 + ng + j * 8 + 2 * tig;
            *(float2*)&Cb[(long long)m0r * N_ + m]       = make_float2(acc[s2][j][0], acc[s2][j][1]);
            *(float2*)&Cb[(long long)(m0r + 8) * N_ + m] = make_float2(acc[s2][j][2], acc[s2][j][3]);
        }
    }
}

// ---------------- tf32-MMA GEMM: out[b] = W(256x256) @ X[b] + epilogue ---------
// A-side fragments via ldmatrix (Wh/Wl [row][k]).
__global__ __launch_bounds__(512) void tgemm_kernel(
    const float* __restrict__ W,
    const float* __restrict__ X, long long xstride,
    float* __restrict__ Co, long long cstride,
    int mode,
    const float* __restrict__ bias,
    const float* __restrict__ gamma, const float* __restrict__ beta,
    const float* __restrict__ mean,  const float* __restrict__ var,
    const float* __restrict__ rscale)
{
    extern __shared__ float sh[];
    float* Wh = sh;                  // [256][68]
    float* Wl = Wh + 256 * 68;       // [256][68]
    float* Xs = Wl + 256 * 68;       // [64][136]

    const int t    = threadIdx.x;
    const int w    = t >> 5;
    const int lane = t & 31;
    const int g    = lane >> 2;
    const int tig  = lane & 3;
    const int mg   = (w & 3) * 64;
    const int ng   = (w >> 2) * 32;
    const int n0   = blockIdx.x * 128;
    const int arow = lane & 15;
    const int ak   = (lane >> 4) << 2;
    const float* Xb = X + (long long)blockIdx.y * xstride;
    float*       Cb = Co + (long long)blockIdx.y * cstride;
    const uint32_t wh_u = s2u(Wh), wl_u = s2u(Wl);

    float acc[4][4][4];
#pragma unroll
    for (int i = 0; i < 4; i++)
#pragma unroll
        for (int j = 0; j < 4; j++)
#pragma unroll
            for (int q = 0; q < 4; q++) acc[i][j][q] = 0.f;

    for (int kc0 = 0; kc0 < 256; kc0 += 64) {
        __syncthreads();
#pragma unroll
        for (int i = 0; i < 8; i++) {
            int idx = t + i * 512; int r = idx >> 4, c4 = (idx & 15) << 2;
            float4 v = *(const float4*)(W + r * 256 + kc0 + c4);
            float4 h; h.x = tf32r(v.x); h.y = tf32r(v.y); h.z = tf32r(v.z); h.w = tf32r(v.w);
            float4 l; l.x = v.x - h.x; l.y = v.y - h.y; l.z = v.z - h.z; l.w = v.w - h.w;
            *(float4*)&Wh[r * 68 + c4] = h;
            *(float4*)&Wl[r * 68 + c4] = l;
        }
#pragma unroll
        for (int i = 0; i < 4; i++) {
            int idx = t + i * 512; int r = idx >> 5, c4 = (idx & 31) << 2;
            float4 v = *(const float4*)(Xb + (long long)(kc0 + r) * N_ + n0 + c4);
            v.x = tf32r(v.x); v.y = tf32r(v.y); v.z = tf32r(v.z); v.w = tf32r(v.w);
            *(float4*)&Xs[r * 136 + c4] = v;
        }
        __syncthreads();

#pragma unroll
        for (int kk = 0; kk < 64; kk += 8) {
            uint32_t b0[4], b1[4];
#pragma unroll
            for (int j = 0; j < 4; j++) {
                b0[j] = __float_as_uint(Xs[(kk + tig)     * 136 + ng + j * 8 + g]);
                b1[j] = __float_as_uint(Xs[(kk + tig + 4) * 136 + ng + j * 8 + g]);
            }
#pragma unroll
            for (int i = 0; i < 4; i++) {
                int row = mg + i * 16;
                uint32_t off = (uint32_t)((row + arow) * 68 + kk + ak) * 4u;
                uint32_t ah0, ah1, ah2, ah3, al0, al1, al2, al3;
                ldsm4(ah0, ah1, ah2, ah3, wh_u + off);
                ldsm4(al0, al1, al2, al3, wl_u + off);
#pragma unroll
                for (int j = 0; j < 4; j++) {
                    mma_tf32(acc[i][j], ah0, ah1, ah2, ah3, b0[j], b1[j]);
                    mma_tf32(acc[i][j], al0, al1, al2, al3, b0[j], b1[j]);
                }
            }
        }
    }

#pragma unroll
    for (int i = 0; i < 4; i++) {
        int m0r = mg + i * 16 + g;
#pragma unroll
        for (int j = 0; j < 4; j++) {
            long long m = n0 + ng + j * 8 + 2 * tig;
            float v0 = acc[i][j][0], v1 = acc[i][j][1];
            float v2 = acc[i][j][2], v3 = acc[i][j][3];
            if (mode == 1) {
                float2 rv = *(const float2*)(rscale + (long long)blockIdx.y * N_ + m);
                float b0v = bias[m0r], b1v = bias[m0r + 8];
                v0 = tf32r((v0 + b0v) * rv.x); v1 = tf32r((v1 + b0v) * rv.y);
                v2 = tf32r((v2 + b1v) * rv.x); v3 = tf32r((v3 + b1v) * rv.y);
            } else {
                float b0v = bias[m0r], b1v = bias[m0r + 8];
                float s0 = gamma[m0r]     * rsqrtf(var[m0r]     + 1e-5f);
                float s1 = gamma[m0r + 8] * rsqrtf(var[m0r + 8] + 1e-5f);
                float u0 = mean[m0r], u1 = mean[m0r + 8];
                float t0 = beta[m0r], t1 = beta[m0r + 8];
                v0 = fmaxf((v0 + b0v - u0) * s0 + t0, 0.f);
                v1 = fmaxf((v1 + b0v - u0) * s0 + t0, 0.f);
                v2 = fmaxf((v2 + b1v - u1) * s1 + t1, 0.f);
                v3 = fmaxf((v3 + b1v - u1) * s1 + t1, 0.f);
            }
            *(float2*)&Cb[(long long)m0r * N_ + m]       = make_float2(v0, v1);
            *(float2*)&Cb[(long long)(m0r + 8) * N_ + m] = make_float2(v2, v3);
        }
    }
}

// ---------------- rowsum: diag (fused) + 3xTF32 scores + exp2, no max ----------
// Pm staged TRANSPOSED [m][72] (k-wise coalesced loads) so B-side uses ldmatrix.
__global__ __launch_bounds__(256, 2) void rowsum_kernel()
{
    extern __shared__ float sh[];
    float* Pn   = sh;                 // [64][136]
    float* Pmh  = Pn + 64 * 136;      // [m 64][k 72]  hi split, transposed
    float* Pml  = Pmh + 64 * 72;      // [m 64][k 72]  lo split
    float* dbuf = Pml + 64 * 72;      // [128] local diag

    const int t    = threadIdx.x;
    const int w    = t >> 5;
    const int lane = t & 31;
    const int g    = lane >> 2;
    const int tig  = lane & 3;
    const int n0   = blockIdx.x * 128;
    const int b    = blockIdx.y;
    const int brow = (lane & 7) + ((lane >> 4) << 3);
    const int bk   = ((lane >> 3) & 1) << 2;
    const float* P = g_P + (long long)b * CQ_ * N_;
    const uint32_t pmh_u = s2u(Pmh), pml_u = s2u(Pml);

#pragma unroll
    for (int i = 0; i < 8; i++) {
        int idx = t + i * 256; int r = idx >> 5, c4 = (idx & 31) << 2;
        *(float4*)&Pn[r * 136 + c4] = *(const float4*)(P + (long long)r * N_ + n0 + c4);
    }
    __syncthreads();

    if (t < 128) {
        float s = 0.f;
#pragma unroll
        for (int q = 0; q < CQ_; q++) {
            float p = Pn[q * 136 + t];
            s += p * p;
        }
        dbuf[t] = s;
        g_diag[b * N_ + n0 + t] = s;
    }
    __syncthreads();

    uint32_t ah0[8], ah1[8], ah2[8], ah3[8];
    uint32_t al0[8], al1[8], al2[8], al3[8];
#pragma unroll
    for (int kc = 0; kc < 8; kc++) {
        float ar0 = Pn[(kc * 8 + tig)     * 136 + w * 16 + g];
        float ar1 = Pn[(kc * 8 + tig)     * 136 + w * 16 + g + 8];
        float ar2 = Pn[(kc * 8 + tig + 4) * 136 + w * 16 + g];
        float ar3 = Pn[(kc * 8 + tig + 4) * 136 + w * 16 + g + 8];
        ah0[kc] = f2tf(ar0); ah1[kc] = f2tf(ar1); ah2[kc] = f2tf(ar2); ah3[kc] = f2tf(ar3);
        al0[kc] = __float_as_uint(ar0 - __uint_as_float(ah0[kc]));
        al1[kc] = __float_as_uint(ar1 - __uint_as_float(ah1[kc]));
        al2[kc] = __float_as_uint(ar2 - __uint_as_float(ah2[kc]));
        al3[kc] = __float_as_uint(ar3 - __uint_as_float(ah3[kc]));
    }

    const int r0 = w * 16 + g, r1 = r0 + 8;
    const float c0 = dbuf[r0];
    const float c1 = dbuf[r1];
    float rsum0 = 0.f, rsum1 = 0.f;

    const int sm = t & 63;           // staging m
    const int sk = (t >> 6) << 2;    // staging k4 base

    for (int m0t = 0; m0t < N_; m0t += 64) {
        __syncthreads();
        // transposed split staging: Pmh/Pml [m][72], k-wise coalesced loads
#pragma unroll
        for (int jj = 0; jj < 4; jj++) {
            int k4 = sk + jj * 16;
            float4 v;
            v.x = P[(long long)(k4 + 0) * N_ + m0t + sm];
            v.y = P[(long long)(k4 + 1) * N_ + m0t + sm];
            v.z = P[(long long)(k4 + 2) * N_ + m0t + sm];
            v.w = P[(long long)(k4 + 3) * N_ + m0t + sm];
            float4 h; h.x = tf32r(v.x); h.y = tf32r(v.y); h.z = tf32r(v.z); h.w = tf32r(v.w);
            float4 l; l.x = v.x - h.x; l.y = v.y - h.y; l.z = v.z - h.z; l.w = v.w - h.w;
            *(float4*)&Pmh[sm * 72 + k4] = h;
            *(float4*)&Pml[sm * 72 + k4] = l;
        }
        __syncthreads();

        float s[8][4];
#pragma unroll
        for (int j = 0; j < 8; j++) {
            s[j][0] = -c0; s[j][1] = -c0; s[j][2] = -c1; s[j][3] = -c1;
        }
#pragma unroll
        for (int kc = 0; kc < 8; kc++) {
#pragma unroll
            for (int jp = 0; jp < 4; jp++) {
                uint32_t off = (uint32_t)((jp * 16 + brow) * 72 + kc * 8 + bk) * 4u;
                uint32_t bh0, bh1, bh2, bh3, bl0, bl1, bl2, bl3;
                ldsm4(bh0, bh1, bh2, bh3, pmh_u + off);
                ldsm4(bl0, bl1, bl2, bl3, pml_u + off);
                mma_tf32(s[2 * jp],     ah0[kc], ah1[kc], ah2[kc], ah3[kc], bh0, bh1);
                mma_tf32(s[2 * jp],     ah0[kc], ah1[kc], ah2[kc], ah3[kc], bl0, bl1);
                mma_tf32(s[2 * jp],     al0[kc], al1[kc], al2[kc], al3[kc], bh0, bh1);
                mma_tf32(s[2 * jp + 1], ah0[kc], ah1[kc], ah2[kc], ah3[kc], bh2, bh3);
                mma_tf32(s[2 * jp + 1], ah0[kc], ah1[kc], ah2[kc], ah3[kc], bl2, bl3);
                mma_tf32(s[2 * jp + 1], al0[kc], al1[kc], al2[kc], al3[kc], bh2, bh3);
            }
        }
#pragma unroll
        for (int j = 0; j < 8; j++) {
            rsum0 += tf32r(ex2(s[j][0])) + tf32r(ex2(s[j][1]));
            rsum1 += tf32r(ex2(s[j][2])) + tf32r(ex2(s[j][3]));
        }
    }

    rsum0 += __shfl_xor_sync(0xffffffffu, rsum0, 1);
    rsum0 += __shfl_xor_sync(0xffffffffu, rsum0, 2);
    rsum1 += __shfl_xor_sync(0xffffffffu, rsum1, 1);
    rsum1 += __shfl_xor_sync(0xffffffffu, rsum1, 2);
    if (tig == 0) {
        g_rinv[b * N_ + n0 + r0] = 1.0f / rsum0;
        g_rinv[b * N_ + n0 + r1] = 1.0f / rsum1;
    }
}

// ---------------- fused attention (round-14, known-good): ldmatrix fragments ---
__global__ __launch_bounds__(512, 1) void attn_kernel(const float* __restrict__ x)
{
    extern __shared__ float sh[];
    float* Pmh  = sh;                    // [m 64][k 68]  hi split, transposed
    float* Pml  = Pmh + 64 * 68;         // [m 64][k 68]  lo split
    float* U    = Pml + 64 * 68;         // union: Pn [k64][n136] | Ae_t [m64][n132]
    float* Vs   = U + 64 * 136;          // [c 256][n 132]
    float* sc   = Vs + 256 * 132;        // [128] diag shift
    float* sri  = sc + 128;              // [128] rinv
    float* part = sri + 128;             // [8][64] colsum partials
    float* ci   = part + 512;            // [64]
    float* Pn   = U;
    float* Ae   = U;

    const int t    = threadIdx.x;
    const int w    = t >> 5;
    const int lane = t & 31;
    const int g    = lane >> 2;
    const int tig  = lane & 3;
    const int wn   = w & 7;
    const int mh   = (w >> 3) * 32;
    const int wc   = (w & 7) * 32;
    const int wm   = (w >> 3) * 32;
    const int m0   = blockIdx.x * 64;
    const int b    = blockIdx.y;

    const int brow = (lane & 7) + ((lane >> 4) << 3);
    const int bk   = ((lane >> 3) & 1) << 2;
    const int arow = lane & 15;
    const int ak   = (lane >> 4) << 2;

    const float* P = g_P + (long long)b * CQ_ * N_;
    const float* V = g_V + (long long)b * C_  * N_;
    const uint32_t pmh_u = s2u(Pmh), pml_u = s2u(Pml);
    const uint32_t ae_u = s2u(Ae), vs_u = s2u(Vs);

    // Pm 64x64: load, split, store TRANSPOSED [m][k]
#pragma unroll
    for (int i = 0; i < 2; i++) {
        int idx = t + i * 512; int r = idx >> 4, c4 = (idx & 15) << 2;   // r=k, c4=m
        float4 v = *(const float4*)(P + (long long)r * N_ + m0 + c4);
        float4 h; h.x = tf32r(v.x); h.y = tf32r(v.y); h.z = tf32r(v.z); h.w = tf32r(v.w);
        Pmh[(c4 + 0) * 68 + r] = h.x; Pmh[(c4 + 1) * 68 + r] = h.y;
        Pmh[(c4 + 2) * 68 + r] = h.z; Pmh[(c4 + 3) * 68 + r] = h.w;
        Pml[(c4 + 0) * 68 + r] = v.x - h.x; Pml[(c4 + 1) * 68 + r] = v.y - h.y;
        Pml[(c4 + 2) * 68 + r] = v.z - h.z; Pml[(c4 + 3) * 68 + r] = v.w - h.w;
    }

    float acc[2][4][4];
#pragma unroll
    for (int s2 = 0; s2 < 2; s2++)
#pragma unroll
        for (int j = 0; j < 4; j++)
#pragma unroll
            for (int q = 0; q < 4; q++) acc[s2][j][q] = 0.f;
    float csum = 0.f;

    for (int n0 = 0; n0 < N_; n0 += 128) {
        __syncthreads();   // S1: prev tile fully consumed
        if (n0 && t < 64) {
#pragma unroll
            for (int q = 0; q < 8; q++) csum += part[q * 64 + t];
        }

#pragma unroll
        for (int i = 0; i < 4; i++) {   // Pn 64x128 -> union
            int idx = t + i * 512; int r = idx >> 5, c4 = (idx & 31) << 2;
            *(float4*)&Pn[r * 136 + c4] = *(const float4*)(P + (long long)r * N_ + n0 + c4);
        }
        if (t < 128) {
            sc[t]  = g_diag[b * N_ + n0 + t];
            sri[t] = g_rinv[b * N_ + n0 + t];
        }

        // Vs chunk 0: LDG now, STS after phase A quarter 0
        float4 pf[4];
#pragma unroll
        for (int i = 0; i < 4; i++) {
            int idx = t + i * 512; int r = idx >> 5, c4 = (idx & 31) << 2;
            pf[i] = *(const float4*)(V + (long long)r * N_ + n0 + c4);
        }
        __syncthreads();   // S2: Pn + stats ready

        // ---- phase A: s = Pn^T Pm - c (B-side via ldmatrix on transposed Pm) ----
        const int r0 = wn * 16 + g, r1 = r0 + 8;
        const float c0v = sc[r0], c1v = sc[r1];
        float s[4][4];
#pragma unroll
        for (int j = 0; j < 4; j++) {
            s[j][0] = -c0v; s[j][1] = -c0v; s[j][2] = -c1v; s[j][3] = -c1v;
        }

#pragma unroll
        for (int quar = 0; quar < 4; quar++) {
#pragma unroll
            for (int kq = 0; kq < 2; kq++) {
                const int kc = quar * 16 + kq * 8;
                float ar0 = Pn[(kc + tig)     * 136 + wn * 16 + g];
                float ar1 = Pn[(kc + tig)     * 136 + wn * 16 + g + 8];
                float ar2 = Pn[(kc + tig + 4) * 136 + wn * 16 + g];
                float ar3 = Pn[(kc + tig + 4) * 136 + wn * 16 + g + 8];
                uint32_t ah0 = f2tf(ar0), ah1 = f2tf(ar1), ah2 = f2tf(ar2), ah3 = f2tf(ar3);
                uint32_t al0 = __float_as_uint(ar0 - __uint_as_float(ah0));
                uint32_t al1 = __float_as_uint(ar1 - __uint_as_float(ah1));
                uint32_t al2 = __float_as_uint(ar2 - __uint_as_float(ah2));
                uint32_t al3 = __float_as_uint(ar3 - __uint_as_float(ah3));
#pragma unroll
                for (int jp = 0; jp < 2; jp++) {
                    uint32_t off = (uint32_t)((mh + jp * 16 + brow) * 68 + kc + bk) * 4u;
                    uint32_t h0, h1, h2, h3, l0, l1, l2, l3;
                    ldsm4(h0, h1, h2, h3, pmh_u + off);
                    ldsm4(l0, l1, l2, l3, pml_u + off);
                    mma_tf32(s[2 * jp],     ah0, ah1, ah2, ah3, h0, h1);
                    mma_tf32(s[2 * jp],     ah0, ah1, ah2, ah3, l0, l1);
                    mma_tf32(s[2 * jp],     al0, al1, al2, al3, h0, h1);
                    mma_tf32(s[2 * jp + 1], ah0, ah1, ah2, ah3, h2, h3);
                    mma_tf32(s[2 * jp + 1], ah0, ah1, ah2, ah3, l2, l3);
                    mma_tf32(s[2 * jp + 1], al0, al1, al2, al3, h2, h3);
                }
            }
            // land Vs chunk `quar`, launch chunk `quar+1`
#pragma unroll
            for (int i = 0; i < 4; i++) {
                int idx = t + (quar * 4 + i) * 512; int r = idx >> 5, c4 = (idx & 31) << 2;
                *(float4*)&Vs[r * 132 + c4] = pf[i];
            }
            if (quar < 3) {
#pragma unroll
                for (int i = 0; i < 4; i++) {
                    int idx = t + ((quar + 1) * 4 + i) * 512; int r = idx >> 5, c4 = (idx & 31) << 2;
                    pf[i] = *(const float4*)(V + (long long)r * N_ + n0 + c4);
                }
            }
        }
        __syncthreads();   // S2b: Pn reads done; union flips to Ae (transposed)

        // exp2 -> Ae_t[m][n] (unnormalized, tf32-rounded)
#pragma unroll
        for (int j = 0; j < 4; j++) {
            int col = mh + j * 8 + 2 * tig;
            Ae[(col + 0) * 132 + r0] = tf32r(ex2(s[j][0]));
            Ae[(col + 1) * 132 + r0] = tf32r(ex2(s[j][1]));
            Ae[(col + 0) * 132 + r1] = tf32r(ex2(s[j][2]));
            Ae[(col + 1) * 132 + r1] = tf32r(ex2(s[j][3]));
        }
        __syncthreads();   // S3: Ae + all Vs chunks ready

        // colsum partials: sum_n rinv[n]*E_t[m][n]
        {
            int q = t >> 6, mq = t & 63;
            float p = 0.f;
#pragma unroll
            for (int nn = 0; nn < 16; nn++)
                p += sri[q * 16 + nn] * Ae[mq * 132 + q * 16 + nn];
            part[q * 64 + mq] = p;
        }

        // ---- phase B: acc[32c][32m] += V' @ Ae (all fragments via ldmatrix) ----
#pragma unroll
        for (int nc = 0; nc < 128; nc += 8) {
            uint32_t e0a, e1a, e2a, e3a, e0b, e1b, e2b, e3b;
            ldsm4(e0a, e1a, e2a, e3a, ae_u + (uint32_t)((wm + brow)      * 132 + nc + bk) * 4u);
            ldsm4(e0b, e1b, e2b, e3b, ae_u + (uint32_t)((wm + 16 + brow) * 132 + nc + bk) * 4u);
#pragma unroll
            for (int s2 = 0; s2 < 2; s2++) {
                uint32_t a0, a1, a2, a3;
                ldsm4(a0, a1, a2, a3, vs_u + (uint32_t)((wc + s2 * 16 + arow) * 132 + nc + ak) * 4u);
                mma_tf32(acc[s2][0], a0, a1, a2, a3, e0a, e1a);
                mma_tf32(acc[s2][1], a0, a1, a2, a3, e2a, e3a);
                mma_tf32(acc[s2][2], a0, a1, a2, a3, e0b, e1b);
                mma_tf32(acc[s2][3], a0, a1, a2, a3, e2b, e3b);
            }
        }
    }

    __syncthreads();
    if (t < 64) {
#pragma unroll
        for (int q = 0; q < 8; q++) csum += part[q * 64 + t];
        ci[t] = 1.0f / (1e-9f + csum);
    }
    __syncthreads();

    // ---- epilogue: R = x - acc * ci ----
    float* R = g_R + (long long)b * C_ * N_;
    const float* xb = x + (long long)b * C_ * N_;
#pragma unroll
    for (int j = 0; j < 4; j++) {
        int mm = wm + j * 8 + 2 * tig;
        float i0 = ci[mm], i1 = ci[mm + 1];
        long long m = m0 + mm;
#pragma unroll
        for (int s2 = 0; s2 < 2; s2++) {
            int ca = wc + s2 * 16 + g, cc = ca + 8;
            float2 xa = *(const float2*)(xb + (long long)ca * N_ + m);
            float2 xc = *(const float2*)(xb + (long long)cc * N_ + m);
            *(float2*)(R + (long long)ca * N_ + m) =
                make_float2(xa.x - acc[s2][j][0] * i0, xa.y - acc[s2][j][1] * i1);
            *(float2*)(R + (long long)cc * N_ + m) =
                make_float2(xc.x - acc[s2][j][2] * i0, xc.y - acc[s2][j][3] * i1);
        }
    }
}

// -------------------------------------------------------------------------------
#define PGEMM_SMEM  ((2 * 64 * 68 + 2 * 64 * 136) * 4)
#define ROWSUM_SMEM ((64 * 136 + 2 * 64 * 72 + 128) * 4)
#define ATTN_SMEM   ((2 * 64 * 68 + 64 * 136 + 256 * 132 + 128 + 128 + 512 + 64) * 4)
#define TGEMM_SMEM  ((2 * 256 * 68 + 64 * 136) * 4)

extern "C" void kernel_launch(void* const* d_in, const int* in_sizes, int n_in,
                              void* d_out, int out_size)
{
    const float* x       = (const float*)d_in[0];
    const float* w_qk    = (const float*)d_in[1];
    const float* w_v     = (const float*)d_in[2];
    const float* b_v     = (const float*)d_in[3];
    const float* w_trans = (const float*)d_in[4];
    const float* b_trans = (const float*)d_in[5];
    const float* gamma   = (const float*)d_in[6];
    const float* beta    = (const float*)d_in[7];
    const float* mean    = (const float*)d_in[8];
    const float* var     = (const float*)d_in[9];
    float* out = (float*)d_out;

    cudaFuncSetAttribute(pgemm_kernel,  cudaFuncAttributeMaxDynamicSharedMemorySize, PGEMM_SMEM);
    cudaFuncSetAttribute(rowsum_kernel, cudaFuncAttributeMaxDynamicSharedMemorySize, ROWSUM_SMEM);
    cudaFuncSetAttribute(attn_kernel,   cudaFuncAttributeMaxDynamicSharedMemorySize, ATTN_SMEM);
    cudaFuncSetAttribute(tgemm_kernel,  cudaFuncAttributeMaxDynamicSharedMemorySize, TGEMM_SMEM);

    void *pP, *pV, *pR, *pRi;
    cudaGetSymbolAddress(&pP,  g_P);
    cudaGetSymbolAddress(&pV,  g_V);
    cudaGetSymbolAddress(&pR,  g_R);
    cudaGetSymbolAddress(&pRi, g_rinv);

    // P' = sqrt(log2e) * w_qk @ x   (4-term split tf32, fp32-equivalent)
    pgemm_kernel<<<dim3(32, 4), 256, PGEMM_SMEM>>>(w_qk, x, (float*)pP);
    // rowsum + fused diag (scores pass 1, diag-shifted)
    rowsum_kernel<<<dim3(32, 4), 256, ROWSUM_SMEM>>>();
    // V' = tf32r((w_v @ x + b_v) * rinv)
    tgemm_kernel<<<dim3(32, 4), 512, TGEMM_SMEM>>>(w_v, x, (long long)C_ * N_,
                                                   (float*)pV, (long long)C_ * N_,
                                                   1, b_v, nullptr, nullptr, nullptr, nullptr,
                                                   (const float*)pRi);
    // fused attention (scores pass 2 + exp + AV + colsum + residual)
    attn_kernel<<<dim3(64, 4), 512, ATTN_SMEM>>>(x);
    // out = ReLU(BN(w_trans @ R + b_trans))
    tgemm_kernel<<<dim3(32, 4), 512, TGEMM_SMEM>>>(w_trans, (const float*)pR, (long long)C_ * N_,
                                                   out, (long long)C_ * N_,
                                                   2, b_trans, gamma, beta, mean, var, nullptr);
}

// round 17
// speedup vs baseline: 1.0225x; 1.0225x over previous
#include <cuda_runtime.h>
#include <math.h>
#include <stdint.h>

#define B_  4
#define C_  256
#define N_  4096
#define CQ_ 64
#define SQRT_LOG2E 1.2011224087864498f   // sqrt(log2(e))

// ---------------- scratch (static __device__ — no allocations allowed) ---------
__device__ float g_P[B_*CQ_*N_];     // P' = sqrt(log2e) * w_qk @ x  (4 MB)
__device__ float g_V[B_*C_*N_];      // V' = tf32r((w_v@x + b_v)*rinv) (16 MB)
__device__ float g_R[B_*C_*N_];      // x - new_features             (16 MB)
__device__ float g_diag[B_*N_];      // c'_n = ||P'_n||^2
__device__ float g_rinv[B_*N_];      // 1 / rowsum

// ---------------- helpers -------------------------------------------------------
__device__ __forceinline__ uint32_t f2tf(float x) {
    uint32_t r;
    asm("cvt.rna.tf32.f32 %0, %1;" : "=r"(r) : "f"(x));
    return r;
}
__device__ __forceinline__ float tf32r(float x) { return __uint_as_float(f2tf(x)); }
__device__ __forceinline__ float ex2(float x) {
    float y;
    asm("ex2.approx.ftz.f32 %0, %1;" : "=f"(y) : "f"(x));
    return y;
}
__device__ __forceinline__ void mma_tf32(float* d,
    uint32_t a0, uint32_t a1, uint32_t a2, uint32_t a3,
    uint32_t b0, uint32_t b1)
{
    asm("mma.sync.aligned.m16n8k8.row.col.f32.tf32.tf32.f32 "
        "{%0,%1,%2,%3}, {%4,%5,%6,%7}, {%8,%9}, {%0,%1,%2,%3};"
        : "+f"(d[0]), "+f"(d[1]), "+f"(d[2]), "+f"(d[3])
        : "r"(a0), "r"(a1), "r"(a2), "r"(a3), "r"(b0), "r"(b1));
}
__device__ __forceinline__ void ldsm4(uint32_t& r0, uint32_t& r1, uint32_t& r2, uint32_t& r3,
                                      uint32_t addr)
{
    asm volatile("ldmatrix.sync.aligned.m8n8.x4.shared.b16 {%0,%1,%2,%3}, [%4];"
        : "=r"(r0), "=r"(r1), "=r"(r2), "=r"(r3) : "r"(addr));
}
__device__ __forceinline__ uint32_t s2u(const void* p) {
    uint32_t a;
    asm("{ .reg .u64 t; cvta.to.shared.u64 t, %1; cvt.u32.u64 %0, t; }" : "=r"(a) : "l"(p));
    return a;
}

// ---------------- P projection: 4-term split tf32 (fp32-equivalent precision) ---
// A-side fragments via ldmatrix (Wh/Wl stored [m][k], coalesced staging).
__global__ __launch_bounds__(256, 2) void pgemm_kernel(
    const float* __restrict__ W, const float* __restrict__ X,
    float* __restrict__ Co)
{
    extern __shared__ float sh[];
    float* Wh = sh;                  // [64][68]
    float* Wl = Wh + 64 * 68;        // [64][68]
    float* Xh = Wl + 64 * 68;        // [64][136]
    float* Xl = Xh + 64 * 136;       // [64][136]

    const int t    = threadIdx.x;
    const int w    = t >> 5;
    const int lane = t & 31;
    const int g    = lane >> 2;
    const int tig  = lane & 3;
    const int mg   = (w & 1) * 32;
    const int ng   = (w >> 1) * 32;
    const int n0   = blockIdx.x * 128;
    const int arow = lane & 15;
    const int ak   = (lane >> 4) << 2;
    const float* Xb = X + (long long)blockIdx.y * C_ * N_;
    float*       Cb = Co + (long long)blockIdx.y * CQ_ * N_;
    const uint32_t wh_u = s2u(Wh), wl_u = s2u(Wl);

    float acc[2][4][4];
#pragma unroll
    for (int i = 0; i < 2; i++)
#pragma unroll
        for (int j = 0; j < 4; j++)
#pragma unroll
            for (int q = 0; q < 4; q++) acc[i][j][q] = 0.f;

    for (int kc0 = 0; kc0 < 256; kc0 += 64) {
        __syncthreads();
#pragma unroll
        for (int i = 0; i < 4; i++) {
            int idx = t + i * 256; int r = idx >> 4, c4 = (idx & 15) << 2;
            float4 v = *(const float4*)(W + r * 256 + kc0 + c4);
            v.x *= SQRT_LOG2E; v.y *= SQRT_LOG2E; v.z *= SQRT_LOG2E; v.w *= SQRT_LOG2E;
            float4 h; h.x = tf32r(v.x); h.y = tf32r(v.y); h.z = tf32r(v.z); h.w = tf32r(v.w);
            float4 l; l.x = v.x - h.x; l.y = v.y - h.y; l.z = v.z - h.z; l.w = v.w - h.w;
            *(float4*)&Wh[r * 68 + c4] = h;
            *(float4*)&Wl[r * 68 + c4] = l;
        }
#pragma unroll
        for (int i = 0; i < 8; i++) {
            int idx = t + i * 256; int r = idx >> 5, c4 = (idx & 31) << 2;
            float4 v = *(const float4*)(Xb + (long long)(kc0 + r) * N_ + n0 + c4);
            float4 h; h.x = tf32r(v.x); h.y = tf32r(v.y); h.z = tf32r(v.z); h.w = tf32r(v.w);
            float4 l; l.x = v.x - h.x; l.y = v.y - h.y; l.z = v.z - h.z; l.w = v.w - h.w;
            *(float4*)&Xh[r * 136 + c4] = h;
            *(float4*)&Xl[r * 136 + c4] = l;
        }
        __syncthreads();

#pragma unroll
        for (int kk = 0; kk < 64; kk += 8) {
            uint32_t bh0[4], bh1[4], bl0[4], bl1[4];
#pragma unroll
            for (int j = 0; j < 4; j++) {
                int col = ng + j * 8 + g;
                bh0[j] = __float_as_uint(Xh[(kk + tig)     * 136 + col]);
                bh1[j] = __float_as_uint(Xh[(kk + tig + 4) * 136 + col]);
                bl0[j] = __float_as_uint(Xl[(kk + tig)     * 136 + col]);
                bl1[j] = __float_as_uint(Xl[(kk + tig + 4) * 136 + col]);
            }
#pragma unroll
            for (int s2 = 0; s2 < 2; s2++) {
                int row = mg + s2 * 16;
                uint32_t off = (uint32_t)((row + arow) * 68 + kk + ak) * 4u;
                uint32_t ah0, ah1, ah2, ah3, al0, al1, al2, al3;
                ldsm4(ah0, ah1, ah2, ah3, wh_u + off);
                ldsm4(al0, al1, al2, al3, wl_u + off);
#pragma unroll
                for (int j = 0; j < 4; j++) {
                    mma_tf32(acc[s2][j], ah0, ah1, ah2, ah3, bh0[j], bh1[j]);
                    mma_tf32(acc[s2][j], ah0, ah1, ah2, ah3, bl0[j], bl1[j]);
                    mma_tf32(acc[s2][j], al0, al1, al2, al3, bh0[j], bh1[j]);
                    mma_tf32(acc[s2][j], al0, al1, al2, al3, bl0[j], bl1[j]);
                }
            }
        }
    }

#pragma unroll
    for (int s2 = 0; s2 < 2; s2++) {
        int m0r = mg + s2 * 16 + g;
#pragma unroll
        for (int j = 0; j < 4; j++) {
            long long m = n0 + ng + j * 8 + 2 * tig;
            *(float2*)&Cb[(long long)m0r * N_ + m]       = make_float2(acc[s2][j][0], acc[s2][j][1]);
            *(float2*)&Cb[(long long)(m0r + 8) * N_ + m] = make_float2(acc[s2][j][2], acc[s2][j][3]);
        }
    }
}

// ---------------- tf32-MMA GEMM: out[b] = W(256x256) @ X[b] + epilogue ---------
// A-side fragments via ldmatrix (Wh/Wl [row][k], coalesced staging).
__global__ __launch_bounds__(512) void tgemm_kernel(
    const float* __restrict__ W,
    const float* __restrict__ X, long long xstride,
    float* __restrict__ Co, long long cstride,
    int mode,
    const float* __restrict__ bias,
    const float* __restrict__ gamma, const float* __restrict__ beta,
    const float* __restrict__ mean,  const float* __restrict__ var,
    const float* __restrict__ rscale)
{
    extern __shared__ float sh[];
    float* Wh = sh;                  // [256][68]
    float* Wl = Wh + 256 * 68;       // [256][68]
    float* Xs = Wl + 256 * 68;       // [64][136]

    const int t    = threadIdx.x;
    const int w    = t >> 5;
    const int lane = t & 31;
    const int g    = lane >> 2;
    const int tig  = lane & 3;
    const int mg   = (w & 3) * 64;
    const int ng   = (w >> 2) * 32;
    const int n0   = blockIdx.x * 128;
    const int arow = lane & 15;
    const int ak   = (lane >> 4) << 2;
    const float* Xb = X + (long long)blockIdx.y * xstride;
    float*       Cb = Co + (long long)blockIdx.y * cstride;
    const uint32_t wh_u = s2u(Wh), wl_u = s2u(Wl);

    float acc[4][4][4];
#pragma unroll
    for (int i = 0; i < 4; i++)
#pragma unroll
        for (int j = 0; j < 4; j++)
#pragma unroll
            for (int q = 0; q < 4; q++) acc[i][j][q] = 0.f;

    for (int kc0 = 0; kc0 < 256; kc0 += 64) {
        __syncthreads();
#pragma unroll
        for (int i = 0; i < 8; i++) {
            int idx = t + i * 512; int r = idx >> 4, c4 = (idx & 15) << 2;
            float4 v = *(const float4*)(W + r * 256 + kc0 + c4);
            float4 h; h.x = tf32r(v.x); h.y = tf32r(v.y); h.z = tf32r(v.z); h.w = tf32r(v.w);
            float4 l; l.x = v.x - h.x; l.y = v.y - h.y; l.z = v.z - h.z; l.w = v.w - h.w;
            *(float4*)&Wh[r * 68 + c4] = h;
            *(float4*)&Wl[r * 68 + c4] = l;
        }
#pragma unroll
        for (int i = 0; i < 4; i++) {
            int idx = t + i * 512; int r = idx >> 5, c4 = (idx & 31) << 2;
            float4 v = *(const float4*)(Xb + (long long)(kc0 + r) * N_ + n0 + c4);
            v.x = tf32r(v.x); v.y = tf32r(v.y); v.z = tf32r(v.z); v.w = tf32r(v.w);
            *(float4*)&Xs[r * 136 + c4] = v;
        }
        __syncthreads();

#pragma unroll
        for (int kk = 0; kk < 64; kk += 8) {
            uint32_t b0[4], b1[4];
#pragma unroll
            for (int j = 0; j < 4; j++) {
                b0[j] = __float_as_uint(Xs[(kk + tig)     * 136 + ng + j * 8 + g]);
                b1[j] = __float_as_uint(Xs[(kk + tig + 4) * 136 + ng + j * 8 + g]);
            }
#pragma unroll
            for (int i = 0; i < 4; i++) {
                int row = mg + i * 16;
                uint32_t off = (uint32_t)((row + arow) * 68 + kk + ak) * 4u;
                uint32_t ah0, ah1, ah2, ah3, al0, al1, al2, al3;
                ldsm4(ah0, ah1, ah2, ah3, wh_u + off);
                ldsm4(al0, al1, al2, al3, wl_u + off);
#pragma unroll
                for (int j = 0; j < 4; j++) {
                    mma_tf32(acc[i][j], ah0, ah1, ah2, ah3, b0[j], b1[j]);
                    mma_tf32(acc[i][j], al0, al1, al2, al3, b0[j], b1[j]);
                }
            }
        }
    }

#pragma unroll
    for (int i = 0; i < 4; i++) {
        int m0r = mg + i * 16 + g;
#pragma unroll
        for (int j = 0; j < 4; j++) {
            long long m = n0 + ng + j * 8 + 2 * tig;
            float v0 = acc[i][j][0], v1 = acc[i][j][1];
            float v2 = acc[i][j][2], v3 = acc[i][j][3];
            if (mode == 1) {
                float2 rv = *(const float2*)(rscale + (long long)blockIdx.y * N_ + m);
                float b0v = bias[m0r], b1v = bias[m0r + 8];
                v0 = tf32r((v0 + b0v) * rv.x); v1 = tf32r((v1 + b0v) * rv.y);
                v2 = tf32r((v2 + b1v) * rv.x); v3 = tf32r((v3 + b1v) * rv.y);
            } else {
                float b0v = bias[m0r], b1v = bias[m0r + 8];
                float s0 = gamma[m0r]     * rsqrtf(var[m0r]     + 1e-5f);
                float s1 = gamma[m0r + 8] * rsqrtf(var[m0r + 8] + 1e-5f);
                float u0 = mean[m0r], u1 = mean[m0r + 8];
                float t0 = beta[m0r], t1 = beta[m0r + 8];
                v0 = fmaxf((v0 + b0v - u0) * s0 + t0, 0.f);
                v1 = fmaxf((v1 + b0v - u0) * s0 + t0, 0.f);
                v2 = fmaxf((v2 + b1v - u1) * s1 + t1, 0.f);
                v3 = fmaxf((v3 + b1v - u1) * s1 + t1, 0.f);
            }
            *(float2*)&Cb[(long long)m0r * N_ + m]       = make_float2(v0, v1);
            *(float2*)&Cb[(long long)(m0r + 8) * N_ + m] = make_float2(v2, v3);
        }
    }
}

// ---------------- rowsum (round-14, known-good): diag + 3xTF32 scores + exp2 ---
__global__ __launch_bounds__(256, 2) void rowsum_kernel()
{
    extern __shared__ float sh[];
    float* Pn   = sh;                 // [64][136]
    float* Pmh  = Pn + 64 * 136;      // [64][72]
    float* Pml  = Pmh + 64 * 72;      // [64][72]
    float* dbuf = Pml + 64 * 72;      // [128] local diag

    const int t    = threadIdx.x;
    const int w    = t >> 5;
    const int lane = t & 31;
    const int g    = lane >> 2;
    const int tig  = lane & 3;
    const int n0   = blockIdx.x * 128;
    const int b    = blockIdx.y;
    const float* P = g_P + (long long)b * CQ_ * N_;

#pragma unroll
    for (int i = 0; i < 8; i++) {
        int idx = t + i * 256; int r = idx >> 5, c4 = (idx & 31) << 2;
        *(float4*)&Pn[r * 136 + c4] = *(const float4*)(P + (long long)r * N_ + n0 + c4);
    }
    __syncthreads();

    if (t < 128) {
        float s = 0.f;
#pragma unroll
        for (int q = 0; q < CQ_; q++) {
            float p = Pn[q * 136 + t];
            s += p * p;
        }
        dbuf[t] = s;
        g_diag[b * N_ + n0 + t] = s;
    }
    __syncthreads();

    uint32_t ah0[8], ah1[8], ah2[8], ah3[8];
    uint32_t al0[8], al1[8], al2[8], al3[8];
#pragma unroll
    for (int kc = 0; kc < 8; kc++) {
        float ar0 = Pn[(kc * 8 + tig)     * 136 + w * 16 + g];
        float ar1 = Pn[(kc * 8 + tig)     * 136 + w * 16 + g + 8];
        float ar2 = Pn[(kc * 8 + tig + 4) * 136 + w * 16 + g];
        float ar3 = Pn[(kc * 8 + tig + 4) * 136 + w * 16 + g + 8];
        ah0[kc] = f2tf(ar0); ah1[kc] = f2tf(ar1); ah2[kc] = f2tf(ar2); ah3[kc] = f2tf(ar3);
        al0[kc] = __float_as_uint(ar0 - __uint_as_float(ah0[kc]));
        al1[kc] = __float_as_uint(ar1 - __uint_as_float(ah1[kc]));
        al2[kc] = __float_as_uint(ar2 - __uint_as_float(ah2[kc]));
        al3[kc] = __float_as_uint(ar3 - __uint_as_float(ah3[kc]));
    }

    const int r0 = w * 16 + g, r1 = r0 + 8;
    const float c0 = dbuf[r0];
    const float c1 = dbuf[r1];
    float rsum0 = 0.f, rsum1 = 0.f;

    for (int m0t = 0; m0t < N_; m0t += 64) {
        __syncthreads();
#pragma unroll
        for (int i = 0; i < 4; i++) {
            int idx = t + i * 256; int r = idx >> 4, c4 = (idx & 15) << 2;
            float4 v = *(const float4*)(P + (long long)r * N_ + m0t + c4);
            float4 h; h.x = tf32r(v.x); h.y = tf32r(v.y); h.z = tf32r(v.z); h.w = tf32r(v.w);
            float4 l; l.x = v.x - h.x; l.y = v.y - h.y; l.z = v.z - h.z; l.w = v.w - h.w;
            *(float4*)&Pmh[r * 72 + c4] = h;
            *(float4*)&Pml[r * 72 + c4] = l;
        }
        __syncthreads();

        float s[8][4];
#pragma unroll
        for (int j = 0; j < 8; j++) {
            s[j][0] = -c0; s[j][1] = -c0; s[j][2] = -c1; s[j][3] = -c1;
        }
#pragma unroll
        for (int kc = 0; kc < 8; kc++) {
#pragma unroll
            for (int j = 0; j < 8; j++) {
                int col = j * 8 + g;
                uint32_t bh0 = __float_as_uint(Pmh[(kc * 8 + tig)     * 72 + col]);
                uint32_t bh1 = __float_as_uint(Pmh[(kc * 8 + tig + 4) * 72 + col]);
                uint32_t bl0 = __float_as_uint(Pml[(kc * 8 + tig)     * 72 + col]);
                uint32_t bl1 = __float_as_uint(Pml[(kc * 8 + tig + 4) * 72 + col]);
                mma_tf32(s[j], ah0[kc], ah1[kc], ah2[kc], ah3[kc], bh0, bh1);
                mma_tf32(s[j], ah0[kc], ah1[kc], ah2[kc], ah3[kc], bl0, bl1);
                mma_tf32(s[j], al0[kc], al1[kc], al2[kc], al3[kc], bh0, bh1);
            }
        }
#pragma unroll
        for (int j = 0; j < 8; j++) {
            rsum0 += tf32r(ex2(s[j][0])) + tf32r(ex2(s[j][1]));
            rsum1 += tf32r(ex2(s[j][2])) + tf32r(ex2(s[j][3]));
        }
    }

    rsum0 += __shfl_xor_sync(0xffffffffu, rsum0, 1);
    rsum0 += __shfl_xor_sync(0xffffffffu, rsum0, 2);
    rsum1 += __shfl_xor_sync(0xffffffffu, rsum1, 1);
    rsum1 += __shfl_xor_sync(0xffffffffu, rsum1, 2);
    if (tig == 0) {
        g_rinv[b * N_ + n0 + r0] = 1.0f / rsum0;
        g_rinv[b * N_ + n0 + r1] = 1.0f / rsum1;
    }
}

// ---------------- fused attention (round-14, known-good): ldmatrix fragments ---
__global__ __launch_bounds__(512, 1) void attn_kernel(const float* __restrict__ x)
{
    extern __shared__ float sh[];
    float* Pmh  = sh;                    // [m 64][k 68]  hi split, transposed
    float* Pml  = Pmh + 64 * 68;         // [m 64][k 68]  lo split
    float* U    = Pml + 64 * 68;         // union: Pn [k64][n136] | Ae_t [m64][n132]
    float* Vs   = U + 64 * 136;          // [c 256][n 132]
    float* sc   = Vs + 256 * 132;        // [128] diag shift
    float* sri  = sc + 128;              // [128] rinv
    float* part = sri + 128;             // [8][64] colsum partials
    float* ci   = part + 512;            // [64]
    float* Pn   = U;
    float* Ae   = U;

    const int t    = threadIdx.x;
    const int w    = t >> 5;
    const int lane = t & 31;
    const int g    = lane >> 2;
    const int tig  = lane & 3;
    const int wn   = w & 7;
    const int mh   = (w >> 3) * 32;
    const int wc   = (w & 7) * 32;
    const int wm   = (w >> 3) * 32;
    const int m0   = blockIdx.x * 64;
    const int b    = blockIdx.y;

    const int brow = (lane & 7) + ((lane >> 4) << 3);
    const int bk   = ((lane >> 3) & 1) << 2;
    const int arow = lane & 15;
    const int ak   = (lane >> 4) << 2;

    const float* P = g_P + (long long)b * CQ_ * N_;
    const float* V = g_V + (long long)b * C_  * N_;
    const uint32_t pmh_u = s2u(Pmh), pml_u = s2u(Pml);
    const uint32_t ae_u = s2u(Ae), vs_u = s2u(Vs);

    // Pm 64x64: load, split, store TRANSPOSED [m][k]
#pragma unroll
    for (int i = 0; i < 2; i++) {
        int idx = t + i * 512; int r = idx >> 4, c4 = (idx & 15) << 2;   // r=k, c4=m
        float4 v = *(const float4*)(P + (long long)r * N_ + m0 + c4);
        float4 h; h.x = tf32r(v.x); h.y = tf32r(v.y); h.z = tf32r(v.z); h.w = tf32r(v.w);
        Pmh[(c4 + 0) * 68 + r] = h.x; Pmh[(c4 + 1) * 68 + r] = h.y;
        Pmh[(c4 + 2) * 68 + r] = h.z; Pmh[(c4 + 3) * 68 + r] = h.w;
        Pml[(c4 + 0) * 68 + r] = v.x - h.x; Pml[(c4 + 1) * 68 + r] = v.y - h.y;
        Pml[(c4 + 2) * 68 + r] = v.z - h.z; Pml[(c4 + 3) * 68 + r] = v.w - h.w;
    }

    float acc[2][4][4];
#pragma unroll
    for (int s2 = 0; s2 < 2; s2++)
#pragma unroll
        for (int j = 0; j < 4; j++)
#pragma unroll
            for (int q = 0; q < 4; q++) acc[s2][j][q] = 0.f;
    float csum = 0.f;

    for (int n0 = 0; n0 < N_; n0 += 128) {
        __syncthreads();   // S1: prev tile fully consumed
        if (n0 && t < 64) {
#pragma unroll
            for (int q = 0; q < 8; q++) csum += part[q * 64 + t];
        }

#pragma unroll
        for (int i = 0; i < 4; i++) {   // Pn 64x128 -> union
            int idx = t + i * 512; int r = idx >> 5, c4 = (idx & 31) << 2;
            *(float4*)&Pn[r * 136 + c4] = *(const float4*)(P + (long long)r * N_ + n0 + c4);
        }
        if (t < 128) {
            sc[t]  = g_diag[b * N_ + n0 + t];
            sri[t] = g_rinv[b * N_ + n0 + t];
        }

        // Vs chunk 0: LDG now, STS after phase A quarter 0
        float4 pf[4];
#pragma unroll
        for (int i = 0; i < 4; i++) {
            int idx = t + i * 512; int r = idx >> 5, c4 = (idx & 31) << 2;
            pf[i] = *(const float4*)(V + (long long)r * N_ + n0 + c4);
        }
        __syncthreads();   // S2: Pn + stats ready

        // ---- phase A: s = Pn^T Pm - c (B-side via ldmatrix on transposed Pm) ----
        const int r0 = wn * 16 + g, r1 = r0 + 8;
        const float c0v = sc[r0], c1v = sc[r1];
        float s[4][4];
#pragma unroll
        for (int j = 0; j < 4; j++) {
            s[j][0] = -c0v; s[j][1] = -c0v; s[j][2] = -c1v; s[j][3] = -c1v;
        }

#pragma unroll
        for (int quar = 0; quar < 4; quar++) {
#pragma unroll
            for (int kq = 0; kq < 2; kq++) {
                const int kc = quar * 16 + kq * 8;
                float ar0 = Pn[(kc + tig)     * 136 + wn * 16 + g];
                float ar1 = Pn[(kc + tig)     * 136 + wn * 16 + g + 8];
                float ar2 = Pn[(kc + tig + 4) * 136 + wn * 16 + g];
                float ar3 = Pn[(kc + tig + 4) * 136 + wn * 16 + g + 8];
                uint32_t ah0 = f2tf(ar0), ah1 = f2tf(ar1), ah2 = f2tf(ar2), ah3 = f2tf(ar3);
                uint32_t al0 = __float_as_uint(ar0 - __uint_as_float(ah0));
                uint32_t al1 = __float_as_uint(ar1 - __uint_as_float(ah1));
                uint32_t al2 = __float_as_uint(ar2 - __uint_as_float(ah2));
                uint32_t al3 = __float_as_uint(ar3 - __uint_as_float(ah3));
#pragma unroll
                for (int jp = 0; jp < 2; jp++) {
                    uint32_t off = (uint32_t)((mh + jp * 16 + brow) * 68 + kc + bk) * 4u;
                    uint32_t h0, h1, h2, h3, l0, l1, l2, l3;
                    ldsm4(h0, h1, h2, h3, pmh_u + off);
                    ldsm4(l0, l1, l2, l3, pml_u + off);
                    mma_tf32(s[2 * jp],     ah0, ah1, ah2, ah3, h0, h1);
                    mma_tf32(s[2 * jp],     ah0, ah1, ah2, ah3, l0, l1);
                    mma_tf32(s[2 * jp],     al0, al1, al2, al3, h0, h1);
                    mma_tf32(s[2 * jp + 1], ah0, ah1, ah2, ah3, h2, h3);
                    mma_tf32(s[2 * jp + 1], ah0, ah1, ah2, ah3, l2, l3);
                    mma_tf32(s[2 * jp + 1], al0, al1, al2, al3, h2, h3);
                }
            }
            // land Vs chunk `quar`, launch chunk `quar+1`
#pragma unroll
            for (int i = 0; i < 4; i++) {
                int idx = t + (quar * 4 + i) * 512; int r = idx >> 5, c4 = (idx & 31) << 2;
                *(float4*)&Vs[r * 132 + c4] = pf[i];
            }
            if (quar < 3) {
#pragma unroll
                for (int i = 0; i < 4; i++) {
                    int idx = t + ((quar + 1) * 4 + i) * 512; int r = idx >> 5, c4 = (idx & 31) << 2;
                    pf[i] = *(const float4*)(V + (long long)r * N_ + n0 + c4);
                }
            }
        }
        __syncthreads();   // S2b: Pn reads done; union flips to Ae (transposed)

        // exp2 -> Ae_t[m][n] (unnormalized, tf32-rounded)
#pragma unroll
        for (int j = 0; j < 4; j++) {
            int col = mh + j * 8 + 2 * tig;
            Ae[(col + 0) * 132 + r0] = tf32r(ex2(s[j][0]));
            Ae[(col + 1) * 132 + r0] = tf32r(ex2(s[j][1]));
            Ae[(col + 0) * 132 + r1] = tf32r(ex2(s[j][2]));
            Ae[(col + 1) * 132 + r1] = tf32r(ex2(s[j][3]));
        }
        __syncthreads();   // S3: Ae + all Vs chunks ready

        // colsum partials: sum_n rinv[n]*E_t[m][n]
        {
            int q = t >> 6, mq = t & 63;
            float p = 0.f;
#pragma unroll
            for (int nn = 0; nn < 16; nn++)
                p += sri[q * 16 + nn] * Ae[mq * 132 + q * 16 + nn];
            part[q * 64 + mq] = p;
        }

        // ---- phase B: acc[32c][32m] += V' @ Ae (all fragments via ldmatrix) ----
#pragma unroll
        for (int nc = 0; nc < 128; nc += 8) {
            uint32_t e0a, e1a, e2a, e3a, e0b, e1b, e2b, e3b;
            ldsm4(e0a, e1a, e2a, e3a, ae_u + (uint32_t)((wm + brow)      * 132 + nc + bk) * 4u);
            ldsm4(e0b, e1b, e2b, e3b, ae_u + (uint32_t)((wm + 16 + brow) * 132 + nc + bk) * 4u);
#pragma unroll
            for (int s2 = 0; s2 < 2; s2++) {
                uint32_t a0, a1, a2, a3;
                ldsm4(a0, a1, a2, a3, vs_u + (uint32_t)((wc + s2 * 16 + arow) * 132 + nc + ak) * 4u);
                mma_tf32(acc[s2][0], a0, a1, a2, a3, e0a, e1a);
                mma_tf32(acc[s2][1], a0, a1, a2, a3, e2a, e3a);
                mma_tf32(acc[s2][2], a0, a1, a2, a3, e0b, e1b);
                mma_tf32(acc[s2][3], a0, a1, a2, a3, e2b, e3b);
            }
        }
    }

    __syncthreads();
    if (t < 64) {
#pragma unroll
        for (int q = 0; q < 8; q++) csum += part[q * 64 + t];
        ci[t] = 1.0f / (1e-9f + csum);
    }
    __syncthreads();

    // ---- epilogue: R = x - acc * ci ----
    float* R = g_R + (long long)b * C_ * N_;
    const float* xb = x + (long long)b * C_ * N_;
#pragma unroll
    for (int j = 0; j < 4; j++) {
        int mm = wm + j * 8 + 2 * tig;
        float i0 = ci[mm], i1 = ci[mm + 1];
        long long m = m0 + mm;
#pragma unroll
        for (int s2 = 0; s2 < 2; s2++) {
            int ca = wc + s2 * 16 + g, cc = ca + 8;
            float2 xa = *(const float2*)(xb + (long long)ca * N_ + m);
            float2 xc = *(const float2*)(xb + (long long)cc * N_ + m);
            *(float2*)(R + (long long)ca * N_ + m) =
                make_float2(xa.x - acc[s2][j][0] * i0, xa.y - acc[s2][j][1] * i1);
            *(float2*)(R + (long long)cc * N_ + m) =
                make_float2(xc.x - acc[s2][j][2] * i0, xc.y - acc[s2][j][3] * i1);
        }
    }
}

// -------------------------------------------------------------------------------
#define PGEMM_SMEM  ((2 * 64 * 68 + 2 * 64 * 136) * 4)
#define ROWSUM_SMEM ((64 * 136 + 2 * 64 * 72 + 128) * 4)
#define ATTN_SMEM   ((2 * 64 * 68 + 64 * 136 + 256 * 132 + 128 + 128 + 512 + 64) * 4)
#define TGEMM_SMEM  ((2 * 256 * 68 + 64 * 136) * 4)

extern "C" void kernel_launch(void* const* d_in, const int* in_sizes, int n_in,
                              void* d_out, int out_size)
{
    const float* x       = (const float*)d_in[0];
    const float* w_qk    = (const float*)d_in[1];
    const float* w_v     = (const float*)d_in[2];
    const float* b_v     = (const float*)d_in[3];
    const float* w_trans = (const float*)d_in[4];
    const float* b_trans = (const float*)d_in[5];
    const float* gamma   = (const float*)d_in[6];
    const float* beta    = (const float*)d_in[7];
    const float* mean    = (const float*)d_in[8];
    const float* var     = (const float*)d_in[9];
    float* out = (float*)d_out;

    cudaFuncSetAttribute(pgemm_kernel,  cudaFuncAttributeMaxDynamicSharedMemorySize, PGEMM_SMEM);
    cudaFuncSetAttribute(rowsum_kernel, cudaFuncAttributeMaxDynamicSharedMemorySize, ROWSUM_SMEM);
    cudaFuncSetAttribute(attn_kernel,   cudaFuncAttributeMaxDynamicSharedMemorySize, ATTN_SMEM);
    cudaFuncSetAttribute(tgemm_kernel,  cudaFuncAttributeMaxDynamicSharedMemorySize, TGEMM_SMEM);

    void *pP, *pV, *pR, *pRi;
    cudaGetSymbolAddress(&pP,  g_P);
    cudaGetSymbolAddress(&pV,  g_V);
    cudaGetSymbolAddress(&pR,  g_R);
    cudaGetSymbolAddress(&pRi, g_rinv);

    // P' = sqrt(log2e) * w_qk @ x   (4-term split tf32, fp32-equivalent)
    pgemm_kernel<<<dim3(32, 4), 256, PGEMM_SMEM>>>(w_qk, x, (float*)pP);
    // rowsum + fused diag (scores pass 1, diag-shifted)
    rowsum_kernel<<<dim3(32, 4), 256, ROWSUM_SMEM>>>();
    // V' = tf32r((w_v @ x + b_v) * rinv)
    tgemm_kernel<<<dim3(32, 4), 512, TGEMM_SMEM>>>(w_v, x, (long long)C_ * N_,
                                                   (float*)pV, (long long)C_ * N_,
                                                   1, b_v, nullptr, nullptr, nullptr, nullptr,
                                                   (const float*)pRi);
    // fused attention (scores pass 2 + exp + AV + colsum + residual)
    attn_kernel<<<dim3(64, 4), 512, ATTN_SMEM>>>(x);
    // out = ReLU(BN(w_trans @ R + b_trans))
    tgemm_kernel<<<dim3(32, 4), 512, TGEMM_SMEM>>>(w_trans, (const float*)pR, (long long)C_ * N_,
                                                   out, (long long)C_ * N_,
                                                   2, b_trans, gamma, beta, mean, var, nullptr);
}